// round 13
// baseline (speedup 1.0000x reference)
#include <cuda_runtime.h>
#include <cuda_fp16.h>
#include <math.h>
#include <stdint.h>

// Problem constants
#define S_LEN   2048
#define HID     4096
#define NH      32
#define NKV     8
#define HD      128
#define QKV_DIM 6144   // NH*HD + 2*NKV*HD
#define QK_COLS 5120   // q+k columns (2-pass); v columns = 1024 (1-pass)
#define GROUPS  4
#define SCALE   0.08838834764831845f   // 1/sqrt(128)

// ---------------------------------------------------------------------------
// Device scratch (no allocations allowed)
// ---------------------------------------------------------------------------
__device__ float g_qkv[S_LEN * QKV_DIM];   // fp32 q,k GEMM out (v unused)
__device__ float g_cos[S_LEN * 64];
__device__ float g_sin[S_LEN * 64];

__device__ __align__(128) __half g_x_hi[S_LEN * HID];
__device__ __align__(128) __half g_x_lo[S_LEN * HID];
__device__ __align__(128) __half g_wqkv[QKV_DIM * HID];
__device__ __align__(128) __half g_wo[HID * HID];
__device__ __align__(128) __half g_qkvsp_hi[S_LEN * QKV_DIM];
__device__ __align__(128) __half g_qkvsp_lo[S_LEN * QKV_DIM];   // lo: Q heads only
__device__ __align__(128) __half g_attn[S_LEN * HID];           // single fp16

// ---------------------------------------------------------------------------
// Helpers
// ---------------------------------------------------------------------------
static __device__ __forceinline__ uint32_t smem_u32(const void* p) {
    uint32_t a;
    asm("{ .reg .u64 t; cvta.to.shared.u64 t, %1; cvt.u32.u64 %0, t; }"
        : "=r"(a) : "l"(p));
    return a;
}

static __device__ __forceinline__ void cp16(uint32_t dst, const void* src) {
    asm volatile("cp.async.cg.shared.global [%0], [%1], 16;"
                 :: "r"(dst), "l"(src));
}

static __device__ __forceinline__ void ldsm_x4(uint32_t& r0, uint32_t& r1,
                                               uint32_t& r2, uint32_t& r3,
                                               uint32_t addr) {
    asm volatile("ldmatrix.sync.aligned.m8n8.x4.shared.b16 {%0,%1,%2,%3}, [%4];"
                 : "=r"(r0), "=r"(r1), "=r"(r2), "=r"(r3) : "r"(addr));
}

static __device__ __forceinline__ void ldsm_x4t(uint32_t& r0, uint32_t& r1,
                                                uint32_t& r2, uint32_t& r3,
                                                uint32_t addr) {
    asm volatile("ldmatrix.sync.aligned.m8n8.x4.trans.shared.b16 {%0,%1,%2,%3}, [%4];"
                 : "=r"(r0), "=r"(r1), "=r"(r2), "=r"(r3) : "r"(addr));
}

static __device__ __forceinline__ void mma16816(float* d, const uint32_t* a,
                                                const uint32_t* b) {
    asm volatile(
        "mma.sync.aligned.m16n8k16.row.col.f32.f16.f16.f32 "
        "{%0,%1,%2,%3}, {%4,%5,%6,%7}, {%8,%9}, {%0,%1,%2,%3};"
        : "+f"(d[0]), "+f"(d[1]), "+f"(d[2]), "+f"(d[3])
        : "r"(a[0]), "r"(a[1]), "r"(a[2]), "r"(a[3]), "r"(b[0]), "r"(b[1]));
}

static __device__ __forceinline__ uint32_t pack_f16x2(float lo, float hi) {
    uint32_t d;
    asm("cvt.rn.f16x2.f32 %0, %1, %2;" : "=r"(d) : "f"(hi), "f"(lo));
    return d;
}
static __device__ __forceinline__ float f16lo_f(uint32_t u) {
    return __half2float(__ushort_as_half((unsigned short)(u & 0xffffu)));
}
static __device__ __forceinline__ float f16hi_f(uint32_t u) {
    return __half2float(__ushort_as_half((unsigned short)(u >> 16)));
}

// ---------------------------------------------------------------------------
// fp32 -> fp16 hi/lo split (8 elems/thread)
// ---------------------------------------------------------------------------
__global__ void convert_split_kernel(const float* __restrict__ src,
                                     __half* __restrict__ hi,
                                     __half* __restrict__ lo, int n8) {
    int i = blockIdx.x * blockDim.x + threadIdx.x;
    if (i >= n8) return;
    size_t o = (size_t)i * 8;
#pragma unroll
    for (int half8 = 0; half8 < 2; half8++) {
        float4 x = *(const float4*)(src + o + half8 * 4);
        uint32_t h0 = pack_f16x2(x.x, x.y);
        uint32_t h1 = pack_f16x2(x.z, x.w);
        uint32_t l0 = pack_f16x2(x.x - f16lo_f(h0), x.y - f16hi_f(h0));
        uint32_t l1 = pack_f16x2(x.z - f16lo_f(h1), x.w - f16hi_f(h1));
        *(uint2*)(hi + o + half8 * 4) = make_uint2(h0, h1);
        *(uint2*)(lo + o + half8 * 4) = make_uint2(l0, l1);
    }
}

// fp32 -> single fp16 (8 elems/thread)
__global__ void convert_half_kernel(const float* __restrict__ src,
                                    __half* __restrict__ dst, int n8) {
    int i = blockIdx.x * blockDim.x + threadIdx.x;
    if (i >= n8) return;
    size_t o = (size_t)i * 8;
    float4 x = *(const float4*)(src + o);
    float4 y = *(const float4*)(src + o + 4);
    *(uint4*)(dst + o) = make_uint4(pack_f16x2(x.x, x.y), pack_f16x2(x.z, x.w),
                                    pack_f16x2(y.x, y.y), pack_f16x2(y.z, y.w));
}

// ---------------------------------------------------------------------------
// RoPE table (verified)
// ---------------------------------------------------------------------------
__global__ void rope_table_kernel(const int* __restrict__ pos_ids) {
    int idx = blockIdx.x * blockDim.x + threadIdx.x;
    if (idx >= S_LEN * 64) return;
    int s = idx >> 6;
    int d = idx & 63;
    float expo = (float)(2 * d) * (1.0f / 128.0f);
    float invf = exp2f(-expo * 16.609640474436813f);   // log2(100000)
    float a = (float)((double)pos_ids[s] * (double)invf);
    double ar = (double)a;
    double k  = rint(ar * 0.15915494309189535);
    ar -= k * 6.283185307179586;
    float r = (float)ar;
    g_cos[idx] = cosf(r);
    g_sin[idx] = sinf(r);
}

// ---------------------------------------------------------------------------
// Post-QKV (q,k heads only now): RoPE, fp16 hi for all, lo for Q heads.
// ---------------------------------------------------------------------------
__global__ void postqkv_kernel(const float* __restrict__ qkv,
                               __half* __restrict__ hi,
                               __half* __restrict__ lo) {
    int idx = blockIdx.x * blockDim.x + threadIdx.x;
    if (idx >= S_LEN * 40 * 32) return;
    int d    = (idx & 31) * 2;
    int rem  = idx >> 5;
    int head = rem % 40;
    int s    = rem / 40;
    size_t base = (size_t)s * QKV_DIM + head * 128;
    float2 x1 = *(const float2*)(qkv + base + d);
    float2 x2 = *(const float2*)(qkv + base + d + 64);
    {
        float2 c  = *(const float2*)(g_cos + (s << 6) + d);
        float2 sn = *(const float2*)(g_sin + (s << 6) + d);
        float y1x = x1.x * c.x - x2.x * sn.x;
        float y1y = x1.y * c.y - x2.y * sn.y;
        float y2x = x2.x * c.x + x1.x * sn.x;
        float y2y = x2.y * c.y + x1.y * sn.y;
        x1 = make_float2(y1x, y1y);
        x2 = make_float2(y2x, y2y);
    }
    uint32_t h1 = pack_f16x2(x1.x, x1.y);
    uint32_t h2 = pack_f16x2(x2.x, x2.y);
    *(uint32_t*)(hi + base + d)      = h1;
    *(uint32_t*)(hi + base + d + 64) = h2;
    if (head < 32) {
        *(uint32_t*)(lo + base + d) =
            pack_f16x2(x1.x - f16lo_f(h1), x1.y - f16hi_f(h1));
        *(uint32_t*)(lo + base + d + 64) =
            pack_f16x2(x2.x - f16lo_f(h2), x2.y - f16hi_f(h2));
    }
}

// ---------------------------------------------------------------------------
// fp16-split GEMM via mma.sync (NT): C = (Ah + Al) . B^T, 2 passes.  [q,k]
// CTA 256x128, BK=32, 256 threads (4x2 warps, warp tile 64x64), 4-stage pipe.
// ---------------------------------------------------------------------------
#define ROWB 80                         // 64B data + 16B pad
#define G_AHI 0
#define G_ALO (256 * ROWB)              // 20480
#define G_B   (2 * 256 * ROWB)          // 40960
#define G_STAGE (G_B + 128 * ROWB)      // 51200
#define GEMM_SMEM (4 * G_STAGE)         // 204800

__global__ __launch_bounds__(256, 1) void gemm_mma_split_kernel(
    const __half* __restrict__ Ahi, const __half* __restrict__ Alo,
    const __half* __restrict__ B,
    float* __restrict__ C, int K, int ldc)
{
    extern __shared__ char smc[];
    uint32_t sb = smem_u32(smc);
    int tid  = threadIdx.x;
    int wid  = tid >> 5;
    int lane = tid & 31;
    int wm = wid >> 1;     // 0..3
    int wn = wid & 1;      // 0..1
    int m0 = blockIdx.x * 256;
    int n0 = blockIdx.y * 128;

    const size_t rs = (size_t)K * 2;
    const char* pAhi = (const char*)Ahi + (size_t)m0 * rs;
    const char* pAlo = (const char*)Alo + (size_t)m0 * rs;
    const char* pB   = (const char*)B   + (size_t)n0 * rs;

    auto load_chunk = [&](int stage, int c) {
        uint32_t base = sb + stage * G_STAGE;
        size_t kb = (size_t)c * 64;
#pragma unroll
        for (int i = 0; i < 8; i++) {
            int f   = tid + i * 256;
            int arr = f >> 10;
            int rem = f & 1023;
            int row = rem >> 2;
            int seg = (rem & 3) * 16;
            uint32_t so = (uint32_t)(row * ROWB + seg) + (arr ? G_ALO : G_AHI);
            const char* p = (arr ? pAlo : pAhi) + (size_t)row * rs + kb + seg;
            cp16(base + so, p);
        }
#pragma unroll
        for (int i = 0; i < 2; i++) {
            int f   = tid + i * 256;
            int row = f >> 2;
            int seg = (f & 3) * 16;
            cp16(base + G_B + (uint32_t)(row * ROWB + seg),
                 pB + (size_t)row * rs + kb + seg);
        }
        asm volatile("cp.async.commit_group;" ::: "memory");
    };

    float acc[32][4];
#pragma unroll
    for (int t = 0; t < 32; t++)
#pragma unroll
        for (int j = 0; j < 4; j++) acc[t][j] = 0.0f;

    uint32_t a_off  = (uint32_t)((wm * 64 + (lane & 15)) * ROWB + (lane >> 4) * 16);
    uint32_t b_base = (uint32_t)((wn * 64 + (lane & 7) + ((lane >> 4) << 3)) * ROWB
                                 + ((lane >> 3) & 1) * 16);

    int nch = K / 32;
    load_chunk(0, 0);
    load_chunk(1, 1);
    load_chunk(2, 2);

    for (int c = 0; c < nch; c++) {
        asm volatile("cp.async.wait_group 2;" ::: "memory");
        __syncthreads();
        if (c + 3 < nch) load_chunk((c + 3) & 3, c + 3);
        else asm volatile("cp.async.commit_group;" ::: "memory");

        uint32_t tb = sb + (c & 3) * G_STAGE;
#pragma unroll
        for (int ks = 0; ks < 2; ks++) {
            uint32_t ko = (uint32_t)(ks * 32);
            uint32_t bh[4][4];
#pragma unroll
            for (int np = 0; np < 4; np++) {
                uint32_t bo = b_base + ko + (uint32_t)(np * 16 * ROWB);
                ldsm_x4(bh[np][0], bh[np][1], bh[np][2], bh[np][3], tb + G_B + bo);
            }
#pragma unroll
            for (int mt = 0; mt < 4; mt++) {
                uint32_t ah[4];
                uint32_t ao = a_off + ko + (uint32_t)(mt * 16 * ROWB);
                ldsm_x4(ah[0], ah[1], ah[2], ah[3], tb + G_AHI + ao);
#pragma unroll
                for (int np = 0; np < 4; np++) {
                    mma16816(acc[mt * 8 + 2 * np],     ah, bh[np]);
                    mma16816(acc[mt * 8 + 2 * np + 1], ah, bh[np] + 2);
                }
            }
#pragma unroll
            for (int mt = 0; mt < 4; mt++) {
                uint32_t al[4];
                uint32_t ao = a_off + ko + (uint32_t)(mt * 16 * ROWB);
                ldsm_x4(al[0], al[1], al[2], al[3], tb + G_ALO + ao);
#pragma unroll
                for (int np = 0; np < 4; np++) {
                    mma16816(acc[mt * 8 + 2 * np],     al, bh[np]);
                    mma16816(acc[mt * 8 + 2 * np + 1], al, bh[np] + 2);
                }
            }
        }
    }

    int mbase = m0 + wm * 64 + (lane >> 2);
    int nbase = n0 + wn * 64 + (lane & 3) * 2;
#pragma unroll
    for (int mt = 0; mt < 4; mt++) {
#pragma unroll
        for (int nt = 0; nt < 8; nt++) {
            float* d = acc[mt * 8 + nt];
            int r = mbase + mt * 16;
            int cc = nbase + nt * 8;
            *(float2*)(C + (size_t)r * ldc + cc)       = make_float2(d[0], d[1]);
            *(float2*)(C + (size_t)(r + 8) * ldc + cc) = make_float2(d[2], d[3]);
        }
    }
}

// ---------------------------------------------------------------------------
// 1-pass fp16 GEMM via mma.sync (NT), fp32 output.   [O-projection]
// ---------------------------------------------------------------------------
#define H_A 0
#define H_B (256 * ROWB)                // 20480
#define H_STAGE (H_B + 128 * ROWB)      // 30720
#define GEMM1_SMEM (4 * H_STAGE)        // 122880

// Shared mainloop body used by both 1-pass variants via macro to avoid
// divergence in maintenance.
#define GEMM1_BODY                                                            \
    extern __shared__ char smc[];                                             \
    uint32_t sb = smem_u32(smc);                                              \
    int tid  = threadIdx.x;                                                   \
    int wid  = tid >> 5;                                                      \
    int lane = tid & 31;                                                      \
    int wm = wid >> 1;                                                        \
    int wn = wid & 1;                                                         \
    int m0 = blockIdx.x * 256;                                                \
    int n0 = blockIdx.y * 128;                                                \
    const size_t rs = (size_t)K * 2;                                          \
    const char* pA = (const char*)A + (size_t)m0 * rs;                        \
    const char* pB = (const char*)B + (size_t)n0 * rs;                        \
    auto load_chunk = [&](int stage, int c) {                                 \
        uint32_t base = sb + stage * H_STAGE;                                 \
        size_t kb = (size_t)c * 64;                                           \
        _Pragma("unroll")                                                     \
        for (int i = 0; i < 4; i++) {                                         \
            int f   = tid + i * 256;                                          \
            int row = f >> 2;                                                 \
            int seg = (f & 3) * 16;                                           \
            cp16(base + H_A + (uint32_t)(row * ROWB + seg),                   \
                 pA + (size_t)row * rs + kb + seg);                           \
        }                                                                     \
        _Pragma("unroll")                                                     \
        for (int i = 0; i < 2; i++) {                                         \
            int f   = tid + i * 256;                                          \
            int row = f >> 2;                                                 \
            int seg = (f & 3) * 16;                                           \
            cp16(base + H_B + (uint32_t)(row * ROWB + seg),                   \
                 pB + (size_t)row * rs + kb + seg);                           \
        }                                                                     \
        asm volatile("cp.async.commit_group;" ::: "memory");                  \
    };                                                                        \
    float acc[32][4];                                                         \
    _Pragma("unroll")                                                         \
    for (int t = 0; t < 32; t++)                                              \
        _Pragma("unroll")                                                     \
        for (int j = 0; j < 4; j++) acc[t][j] = 0.0f;                         \
    uint32_t a_off  = (uint32_t)((wm * 64 + (lane & 15)) * ROWB               \
                                 + (lane >> 4) * 16);                         \
    uint32_t b_base = (uint32_t)((wn * 64 + (lane & 7)                        \
                                  + ((lane >> 4) << 3)) * ROWB                \
                                 + ((lane >> 3) & 1) * 16);                   \
    int nch = K / 32;                                                         \
    load_chunk(0, 0);                                                         \
    load_chunk(1, 1);                                                         \
    load_chunk(2, 2);                                                         \
    for (int c = 0; c < nch; c++) {                                           \
        asm volatile("cp.async.wait_group 2;" ::: "memory");                  \
        __syncthreads();                                                      \
        if (c + 3 < nch) load_chunk((c + 3) & 3, c + 3);                      \
        else asm volatile("cp.async.commit_group;" ::: "memory");             \
        uint32_t tb = sb + (c & 3) * H_STAGE;                                 \
        _Pragma("unroll")                                                     \
        for (int ks = 0; ks < 2; ks++) {                                      \
            uint32_t ko = (uint32_t)(ks * 32);                                \
            uint32_t bh[4][4];                                                \
            _Pragma("unroll")                                                 \
            for (int np = 0; np < 4; np++) {                                  \
                uint32_t bo = b_base + ko + (uint32_t)(np * 16 * ROWB);       \
                ldsm_x4(bh[np][0], bh[np][1], bh[np][2], bh[np][3],           \
                        tb + H_B + bo);                                       \
            }                                                                 \
            _Pragma("unroll")                                                 \
            for (int mt = 0; mt < 4; mt++) {                                  \
                uint32_t ah[4];                                               \
                uint32_t ao = a_off + ko + (uint32_t)(mt * 16 * ROWB);        \
                ldsm_x4(ah[0], ah[1], ah[2], ah[3], tb + H_A + ao);           \
                _Pragma("unroll")                                             \
                for (int np = 0; np < 4; np++) {                              \
                    mma16816(acc[mt * 8 + 2 * np],     ah, bh[np]);           \
                    mma16816(acc[mt * 8 + 2 * np + 1], ah, bh[np] + 2);       \
                }                                                             \
            }                                                                 \
        }                                                                     \
    }                                                                         \
    int mbase = m0 + wm * 64 + (lane >> 2);                                   \
    int nbase = n0 + wn * 64 + (lane & 3) * 2;

__global__ __launch_bounds__(256, 1) void gemm_mma_kernel(
    const __half* __restrict__ A, const __half* __restrict__ B,
    float* __restrict__ C, int K, int ldc)
{
    GEMM1_BODY
#pragma unroll
    for (int mt = 0; mt < 4; mt++) {
#pragma unroll
        for (int nt = 0; nt < 8; nt++) {
            float* d = acc[mt * 8 + nt];
            int r = mbase + mt * 16;
            int cc = nbase + nt * 8;
            *(float2*)(C + (size_t)r * ldc + cc)       = make_float2(d[0], d[1]);
            *(float2*)(C + (size_t)(r + 8) * ldc + cc) = make_float2(d[2], d[3]);
        }
    }
}

// 1-pass GEMM with fp16 output (for V slice of QKV)
__global__ __launch_bounds__(256, 1) void gemm_mma_h_kernel(
    const __half* __restrict__ A, const __half* __restrict__ B,
    __half* __restrict__ C, int K, int ldc)
{
    GEMM1_BODY
#pragma unroll
    for (int mt = 0; mt < 4; mt++) {
#pragma unroll
        for (int nt = 0; nt < 8; nt++) {
            float* d = acc[mt * 8 + nt];
            int r = mbase + mt * 16;
            int cc = nbase + nt * 8;
            *(uint32_t*)(C + (size_t)r * ldc + cc)       = pack_f16x2(d[0], d[1]);
            *(uint32_t*)(C + (size_t)(r + 8) * ldc + cc) = pack_f16x2(d[2], d[3]);
        }
    }
}

// ---------------------------------------------------------------------------
// Tensor-core flash attention (causal, GQA).
// QK^T: 2-pass (Q hi+lo, K single).  PV: 1-pass.  Output: single fp16.
// Double-buffered K/V, Q fragments register-cached.  (verified R9)
// ---------------------------------------------------------------------------
#define AROWB 272
#define A_QH 0
#define A_QL (128 * AROWB)                  // 34816
#define A_KV0 (2 * 128 * AROWB)             // 69632
#define KV_VOFF (64 * AROWB)                // 17408
#define KV_STAGE (128 * AROWB)              // 34816
#define ATTN_SMEM (A_KV0 + 2 * KV_STAGE)    // 139264

__global__ __launch_bounds__(256, 1) void attn_mma_kernel(
    const __half* __restrict__ qhi, const __half* __restrict__ qlo,
    __half* __restrict__ o)
{
    extern __shared__ char smc[];
    uint32_t sb = smem_u32(smc);
    int tid  = threadIdx.x;
    int w    = tid >> 5;
    int lane = tid & 31;
    int h    = blockIdx.y;
    int bx   = (int)gridDim.x - 1 - (int)blockIdx.x;   // heavy tiles first
    int q0   = bx * 128;
    int kvh  = h >> 2;

    auto load_kv = [&](int stage, int kt) {
        int k0 = kt * 64;
        uint32_t kbase = sb + A_KV0 + stage * KV_STAGE;
#pragma unroll
        for (int i = 0; i < 8; i++) {
            int f   = tid + i * 256;
            int arr = f >> 10;          // 0 K, 1 V
            int rem = f & 1023;
            int row = rem >> 4;
            int seg = rem & 15;
            int off = arr ? (HID + NKV * HD) : HID;
            const __half* src =
                qhi + (size_t)(k0 + row) * QKV_DIM + off + kvh * HD + seg * 8;
            cp16(kbase + (arr ? KV_VOFF : 0) + row * AROWB + seg * 16, src);
        }
        asm volatile("cp.async.commit_group;" ::: "memory");
    };

    // Q tile hi+lo, committed together with KV tile 0
#pragma unroll
    for (int i = 0; i < 16; i++) {
        int f   = tid + i * 256;
        int arr = f >> 11;
        int rem = f & 2047;
        int row = rem >> 4;
        int seg = rem & 15;
        const __half* src =
            (arr ? qlo : qhi) + (size_t)(q0 + row) * QKV_DIM + h * HD + seg * 8;
        cp16(sb + (arr ? A_QL : A_QH) + row * AROWB + seg * 16, src);
    }
    load_kv(0, 0);
    load_kv(1, 1);

    asm volatile("cp.async.wait_group 1;" ::: "memory");
    __syncthreads();

    // cache Q fragments in registers (loaded once)
    uint32_t qfh[8][4], qfl[8][4];
#pragma unroll
    for (int ks = 0; ks < 8; ks++) {
        uint32_t ao = (uint32_t)((16 * w + (lane & 15)) * AROWB
                                 + ks * 32 + (lane >> 4) * 16);
        ldsm_x4(qfh[ks][0], qfh[ks][1], qfh[ks][2], qfh[ks][3], sb + A_QH + ao);
        ldsm_x4(qfl[ks][0], qfl[ks][1], qfl[ks][2], qfl[ks][3], sb + A_QL + ao);
    }

    float oacc[16][4];
#pragma unroll
    for (int t = 0; t < 16; t++)
#pragma unroll
        for (int j = 0; j < 4; j++) oacc[t][j] = 0.0f;
    float mrow[2] = {-1e30f, -1e30f};
    float lrow[2] = {0.0f, 0.0f};

    int wmin = q0 + 16 * w;
    int nkt  = 2 * (bx + 1);

    for (int kt = 0; kt < nkt; kt++) {
        int buf = kt & 1;
        int k0  = kt * 64;

        if (k0 <= wmin + 15) {
            uint32_t kvb = sb + A_KV0 + buf * KV_STAGE;
            float sacc[8][4];
#pragma unroll
            for (int t = 0; t < 8; t++)
#pragma unroll
                for (int j = 0; j < 4; j++) sacc[t][j] = 0.0f;

            // ---- S = Q . K^T (2 passes, Q from registers)
#pragma unroll
            for (int ks = 0; ks < 8; ks++) {
#pragma unroll
                for (int np = 0; np < 4; np++) {
                    uint32_t kh_[4];
                    uint32_t bo = (uint32_t)((np * 16 + (lane & 7)
                                              + ((lane >> 4) << 3)) * AROWB
                                             + ks * 32 + ((lane >> 3) & 1) * 16);
                    ldsm_x4(kh_[0], kh_[1], kh_[2], kh_[3], kvb + bo);
                    mma16816(sacc[2 * np],     qfh[ks], kh_);
                    mma16816(sacc[2 * np],     qfl[ks], kh_);
                    mma16816(sacc[2 * np + 1], qfh[ks], kh_ + 2);
                    mma16816(sacc[2 * np + 1], qfl[ks], kh_ + 2);
                }
            }

            // ---- scale
#pragma unroll
            for (int nt = 0; nt < 8; nt++)
#pragma unroll
                for (int j = 0; j < 4; j++) sacc[nt][j] *= SCALE;

            // ---- causal mask
            int r1 = wmin + (lane >> 2);
            if (k0 + 63 > wmin) {
#pragma unroll
                for (int nt = 0; nt < 8; nt++) {
                    int c0 = k0 + nt * 8 + (lane & 3) * 2;
                    if (c0     > r1)     sacc[nt][0] = -1e30f;
                    if (c0 + 1 > r1)     sacc[nt][1] = -1e30f;
                    if (c0     > r1 + 8) sacc[nt][2] = -1e30f;
                    if (c0 + 1 > r1 + 8) sacc[nt][3] = -1e30f;
                }
            }

            // ---- online softmax
#pragma unroll
            for (int hf = 0; hf < 2; hf++) {
                float mx = -1e30f;
#pragma unroll
                for (int nt = 0; nt < 8; nt++)
                    mx = fmaxf(mx, fmaxf(sacc[nt][2 * hf], sacc[nt][2 * hf + 1]));
                mx = fmaxf(mx, __shfl_xor_sync(0xffffffffu, mx, 1));
                mx = fmaxf(mx, __shfl_xor_sync(0xffffffffu, mx, 2));
                float mn   = fmaxf(mrow[hf], mx);
                float corr = __expf(mrow[hf] - mn);
                mrow[hf] = mn;
                float sum = 0.0f;
#pragma unroll
                for (int nt = 0; nt < 8; nt++) {
                    float p0 = __expf(sacc[nt][2 * hf]     - mn);
                    float p1 = __expf(sacc[nt][2 * hf + 1] - mn);
                    sacc[nt][2 * hf]     = p0;
                    sacc[nt][2 * hf + 1] = p1;
                    sum += p0 + p1;
                }
                sum += __shfl_xor_sync(0xffffffffu, sum, 1);
                sum += __shfl_xor_sync(0xffffffffu, sum, 2);
                lrow[hf] = lrow[hf] * corr + sum;
#pragma unroll
                for (int nt = 0; nt < 16; nt++) {
                    oacc[nt][2 * hf]     *= corr;
                    oacc[nt][2 * hf + 1] *= corr;
                }
            }

            // ---- O += P . V (1 pass)
#pragma unroll
            for (int j = 0; j < 4; j++) {
                uint32_t ph_[4];
                ph_[0] = pack_f16x2(sacc[2 * j][0],     sacc[2 * j][1]);
                ph_[1] = pack_f16x2(sacc[2 * j][2],     sacc[2 * j][3]);
                ph_[2] = pack_f16x2(sacc[2 * j + 1][0], sacc[2 * j + 1][1]);
                ph_[3] = pack_f16x2(sacc[2 * j + 1][2], sacc[2 * j + 1][3]);
#pragma unroll
                for (int np = 0; np < 8; np++) {
                    uint32_t vh_[4];
                    uint32_t vo = (uint32_t)((j * 16 + (lane & 7)
                                              + ((lane >> 3) & 1) * 8) * AROWB
                                             + (np * 16 + ((lane >> 4) << 3)) * 2);
                    ldsm_x4t(vh_[0], vh_[1], vh_[2], vh_[3], kvb + KV_VOFF + vo);
                    mma16816(oacc[2 * np],     ph_, vh_);
                    mma16816(oacc[2 * np + 1], ph_, vh_ + 2);
                }
            }
        }
        __syncthreads();

        if (kt + 2 < nkt) load_kv(buf, kt + 2);
        if (kt + 1 < nkt) {
            asm volatile("cp.async.wait_group %0;" :: "n"(1) : "memory");
        }
        if (kt + 1 < nkt && kt + 2 >= nkt) {
            asm volatile("cp.async.wait_group 0;" ::: "memory");
        }
        if (kt + 1 < nkt) __syncthreads();
    }

    // ---- epilogue: normalize + single fp16 write
    float inv0 = 1.0f / lrow[0];
    float inv1 = 1.0f / lrow[1];
    int r1 = q0 + 16 * w + (lane >> 2);
    size_t base1 = (size_t)r1 * HID + h * HD + (lane & 3) * 2;
    size_t base2 = base1 + (size_t)8 * HID;
#pragma unroll
    for (int nt = 0; nt < 16; nt++) {
        *(uint32_t*)(o + base1 + nt * 8) =
            pack_f16x2(oacc[nt][0] * inv0, oacc[nt][1] * inv0);
        *(uint32_t*)(o + base2 + nt * 8) =
            pack_f16x2(oacc[nt][2] * inv1, oacc[nt][3] * inv1);
    }
}

// ---------------------------------------------------------------------------
// Launch
// ---------------------------------------------------------------------------
extern "C" void kernel_launch(void* const* d_in, const int* in_sizes, int n_in,
                              void* d_out, int out_size)
{
    (void)in_sizes; (void)n_in; (void)out_size;
    const float* x     = (const float*)d_in[0];
    const int*   pos   = (const int*)d_in[1];
    const float* w_qkv = (const float*)d_in[2];
    const float* w_o   = (const float*)d_in[3];
    float*       out   = (float*)d_out;

    void *p_qkv, *p_xh, *p_xl, *p_wq, *p_wo, *p_sph, *p_spl, *p_attn;
    cudaGetSymbolAddress(&p_qkv, g_qkv);
    cudaGetSymbolAddress(&p_xh, g_x_hi);
    cudaGetSymbolAddress(&p_xl, g_x_lo);
    cudaGetSymbolAddress(&p_wq, g_wqkv);
    cudaGetSymbolAddress(&p_wo, g_wo);
    cudaGetSymbolAddress(&p_sph, g_qkvsp_hi);
    cudaGetSymbolAddress(&p_spl, g_qkvsp_lo);
    cudaGetSymbolAddress(&p_attn, g_attn);
    float* qkv = (float*)p_qkv;

    cudaFuncSetAttribute(gemm_mma_split_kernel,
                         cudaFuncAttributeMaxDynamicSharedMemorySize, GEMM_SMEM);
    cudaFuncSetAttribute(gemm_mma_kernel,
                         cudaFuncAttributeMaxDynamicSharedMemorySize, GEMM1_SMEM);
    cudaFuncSetAttribute(gemm_mma_h_kernel,
                         cudaFuncAttributeMaxDynamicSharedMemorySize, GEMM1_SMEM);
    cudaFuncSetAttribute(attn_mma_kernel,
                         cudaFuncAttributeMaxDynamicSharedMemorySize, ATTN_SMEM);

    // RoPE table
    rope_table_kernel<<<(S_LEN * 64 + 255) / 256, 256>>>(pos);

    // Converts
    {
        int n1 = S_LEN * HID / 8;
        convert_split_kernel<<<(n1 + 255) / 256, 256>>>(
            x, (__half*)p_xh, (__half*)p_xl, n1);
        int n2 = QKV_DIM * HID / 8;
        convert_half_kernel<<<(n2 + 255) / 256, 256>>>(w_qkv, (__half*)p_wq, n2);
        int n3 = HID * HID / 8;
        convert_half_kernel<<<(n3 + 255) / 256, 256>>>(w_o, (__half*)p_wo, n3);
    }

    // q,k projection (2-pass split, columns [0, 5120))
    gemm_mma_split_kernel<<<dim3(S_LEN / 256, QK_COLS / 128), 256, GEMM_SMEM>>>(
        (const __half*)p_xh, (const __half*)p_xl, (const __half*)p_wq,
        qkv, HID, QKV_DIM);

    // v projection (1-pass, fp16 out, columns [5120, 6144))
    gemm_mma_h_kernel<<<dim3(S_LEN / 256, (QKV_DIM - QK_COLS) / 128), 256,
                       GEMM1_SMEM>>>(
        (const __half*)p_xh, (const __half*)p_wq + (size_t)QK_COLS * HID,
        (__half*)p_sph + QK_COLS, HID, QKV_DIM);

    // RoPE + split q,k
    postqkv_kernel<<<(S_LEN * 40 * 32 + 255) / 256, 256>>>(
        qkv, (__half*)p_sph, (__half*)p_spl);

    // Tensor-core flash attention (single-fp16 output)
    attn_mma_kernel<<<dim3(S_LEN / 128, NH), 256, ATTN_SMEM>>>(
        (const __half*)p_sph, (const __half*)p_spl, (__half*)p_attn);

    // Output projection (1-pass, fp32 out)
    gemm_mma_kernel<<<dim3(S_LEN / 256, HID / 128), 256, GEMM1_SMEM>>>(
        (const __half*)p_attn, (const __half*)p_wo, out, HID, HID);
}

// round 14
// speedup vs baseline: 1.1104x; 1.1104x over previous
#include <cuda_runtime.h>
#include <cuda_fp16.h>
#include <math.h>
#include <stdint.h>

// Problem constants
#define S_LEN   2048
#define HID     4096
#define NH      32
#define NKV     8
#define HD      128
#define QKV_DIM 6144   // NH*HD + 2*NKV*HD
#define QK_COLS 5120   // q+k columns (2-pass); v columns = 1024 (1-pass)
#define GROUPS  4
#define SCALE   0.08838834764831845f   // 1/sqrt(128)

// ---------------------------------------------------------------------------
// Device scratch (no allocations allowed)
// ---------------------------------------------------------------------------
__device__ float g_qkv[S_LEN * QKV_DIM];   // fp32 q,k GEMM out (v unused)
__device__ float g_cos[S_LEN * 64];
__device__ float g_sin[S_LEN * 64];

__device__ __align__(128) __half g_x_hi[S_LEN * HID];
__device__ __align__(128) __half g_x_lo[S_LEN * HID];
__device__ __align__(128) __half g_wqkv[QKV_DIM * HID];
__device__ __align__(128) __half g_wo[HID * HID];
__device__ __align__(128) __half g_qkvsp_hi[S_LEN * QKV_DIM];
__device__ __align__(128) __half g_qkvsp_lo[S_LEN * QKV_DIM];   // lo: Q heads only
__device__ __align__(128) __half g_attn[S_LEN * HID];           // single fp16

// ---------------------------------------------------------------------------
// Helpers
// ---------------------------------------------------------------------------
static __device__ __forceinline__ uint32_t smem_u32(const void* p) {
    uint32_t a;
    asm("{ .reg .u64 t; cvta.to.shared.u64 t, %1; cvt.u32.u64 %0, t; }"
        : "=r"(a) : "l"(p));
    return a;
}

static __device__ __forceinline__ void cp16(uint32_t dst, const void* src) {
    asm volatile("cp.async.cg.shared.global [%0], [%1], 16;"
                 :: "r"(dst), "l"(src));
}

static __device__ __forceinline__ void ldsm_x4(uint32_t& r0, uint32_t& r1,
                                               uint32_t& r2, uint32_t& r3,
                                               uint32_t addr) {
    asm volatile("ldmatrix.sync.aligned.m8n8.x4.shared.b16 {%0,%1,%2,%3}, [%4];"
                 : "=r"(r0), "=r"(r1), "=r"(r2), "=r"(r3) : "r"(addr));
}

static __device__ __forceinline__ void ldsm_x4t(uint32_t& r0, uint32_t& r1,
                                                uint32_t& r2, uint32_t& r3,
                                                uint32_t addr) {
    asm volatile("ldmatrix.sync.aligned.m8n8.x4.trans.shared.b16 {%0,%1,%2,%3}, [%4];"
                 : "=r"(r0), "=r"(r1), "=r"(r2), "=r"(r3) : "r"(addr));
}

static __device__ __forceinline__ void mma16816(float* d, const uint32_t* a,
                                                const uint32_t* b) {
    asm volatile(
        "mma.sync.aligned.m16n8k16.row.col.f32.f16.f16.f32 "
        "{%0,%1,%2,%3}, {%4,%5,%6,%7}, {%8,%9}, {%0,%1,%2,%3};"
        : "+f"(d[0]), "+f"(d[1]), "+f"(d[2]), "+f"(d[3])
        : "r"(a[0]), "r"(a[1]), "r"(a[2]), "r"(a[3]), "r"(b[0]), "r"(b[1]));
}

static __device__ __forceinline__ uint32_t pack_f16x2(float lo, float hi) {
    uint32_t d;
    asm("cvt.rn.f16x2.f32 %0, %1, %2;" : "=r"(d) : "f"(hi), "f"(lo));
    return d;
}
static __device__ __forceinline__ float f16lo_f(uint32_t u) {
    return __half2float(__ushort_as_half((unsigned short)(u & 0xffffu)));
}
static __device__ __forceinline__ float f16hi_f(uint32_t u) {
    return __half2float(__ushort_as_half((unsigned short)(u >> 16)));
}

// ---------------------------------------------------------------------------
// fp32 -> fp16 hi/lo split (8 elems/thread)
// ---------------------------------------------------------------------------
__global__ void convert_split_kernel(const float* __restrict__ src,
                                     __half* __restrict__ hi,
                                     __half* __restrict__ lo, int n8) {
    int i = blockIdx.x * blockDim.x + threadIdx.x;
    if (i >= n8) return;
    size_t o = (size_t)i * 8;
#pragma unroll
    for (int half8 = 0; half8 < 2; half8++) {
        float4 x = *(const float4*)(src + o + half8 * 4);
        uint32_t h0 = pack_f16x2(x.x, x.y);
        uint32_t h1 = pack_f16x2(x.z, x.w);
        uint32_t l0 = pack_f16x2(x.x - f16lo_f(h0), x.y - f16hi_f(h0));
        uint32_t l1 = pack_f16x2(x.z - f16lo_f(h1), x.w - f16hi_f(h1));
        *(uint2*)(hi + o + half8 * 4) = make_uint2(h0, h1);
        *(uint2*)(lo + o + half8 * 4) = make_uint2(l0, l1);
    }
}

// fp32 -> single fp16 (8 elems/thread)
__global__ void convert_half_kernel(const float* __restrict__ src,
                                    __half* __restrict__ dst, int n8) {
    int i = blockIdx.x * blockDim.x + threadIdx.x;
    if (i >= n8) return;
    size_t o = (size_t)i * 8;
    float4 x = *(const float4*)(src + o);
    float4 y = *(const float4*)(src + o + 4);
    *(uint4*)(dst + o) = make_uint4(pack_f16x2(x.x, x.y), pack_f16x2(x.z, x.w),
                                    pack_f16x2(y.x, y.y), pack_f16x2(y.z, y.w));
}

// ---------------------------------------------------------------------------
// RoPE table (verified)
// ---------------------------------------------------------------------------
__global__ void rope_table_kernel(const int* __restrict__ pos_ids) {
    int idx = blockIdx.x * blockDim.x + threadIdx.x;
    if (idx >= S_LEN * 64) return;
    int s = idx >> 6;
    int d = idx & 63;
    float expo = (float)(2 * d) * (1.0f / 128.0f);
    float invf = exp2f(-expo * 16.609640474436813f);   // log2(100000)
    float a = (float)((double)pos_ids[s] * (double)invf);
    double ar = (double)a;
    double k  = rint(ar * 0.15915494309189535);
    ar -= k * 6.283185307179586;
    float r = (float)ar;
    g_cos[idx] = cosf(r);
    g_sin[idx] = sinf(r);
}

// ---------------------------------------------------------------------------
// Post-QKV (q,k heads only): RoPE, fp16 hi for all, lo for Q heads.
// ---------------------------------------------------------------------------
__global__ void postqkv_kernel(const float* __restrict__ qkv,
                               __half* __restrict__ hi,
                               __half* __restrict__ lo) {
    int idx = blockIdx.x * blockDim.x + threadIdx.x;
    if (idx >= S_LEN * 40 * 32) return;
    int d    = (idx & 31) * 2;
    int rem  = idx >> 5;
    int head = rem % 40;
    int s    = rem / 40;
    size_t base = (size_t)s * QKV_DIM + head * 128;
    float2 x1 = *(const float2*)(qkv + base + d);
    float2 x2 = *(const float2*)(qkv + base + d + 64);
    {
        float2 c  = *(const float2*)(g_cos + (s << 6) + d);
        float2 sn = *(const float2*)(g_sin + (s << 6) + d);
        float y1x = x1.x * c.x - x2.x * sn.x;
        float y1y = x1.y * c.y - x2.y * sn.y;
        float y2x = x2.x * c.x + x1.x * sn.x;
        float y2y = x2.y * c.y + x1.y * sn.y;
        x1 = make_float2(y1x, y1y);
        x2 = make_float2(y2x, y2y);
    }
    uint32_t h1 = pack_f16x2(x1.x, x1.y);
    uint32_t h2 = pack_f16x2(x2.x, x2.y);
    *(uint32_t*)(hi + base + d)      = h1;
    *(uint32_t*)(hi + base + d + 64) = h2;
    if (head < 32) {
        *(uint32_t*)(lo + base + d) =
            pack_f16x2(x1.x - f16lo_f(h1), x1.y - f16hi_f(h1));
        *(uint32_t*)(lo + base + d + 64) =
            pack_f16x2(x2.x - f16lo_f(h2), x2.y - f16hi_f(h2));
    }
}

// ---------------------------------------------------------------------------
// Fused QKV GEMM via mma.sync (NT).
// Columns [0, 5120): C = (Ah + Al).B^T, fp32 out (2 passes).
// Columns [5120, 6144): C = Ah.B^T, fp16 out (1 pass, V slice).
// CTA 256x128, BK=32, 256 threads (4x2 warps, warp tile 64x64), 4-stage pipe.
// ---------------------------------------------------------------------------
#define ROWB 80                         // 64B data + 16B pad
#define G_AHI 0
#define G_ALO (256 * ROWB)              // 20480
#define G_B   (2 * 256 * ROWB)          // 40960
#define G_STAGE (G_B + 128 * ROWB)      // 51200
#define GEMM_SMEM (4 * G_STAGE)         // 204800

__global__ __launch_bounds__(256, 1) void gemm_qkv_fused_kernel(
    const __half* __restrict__ Ahi, const __half* __restrict__ Alo,
    const __half* __restrict__ B,
    float* __restrict__ Cf, __half* __restrict__ Ch, int K, int ldc)
{
    extern __shared__ char smc[];
    uint32_t sb = smem_u32(smc);
    int tid  = threadIdx.x;
    int wid  = tid >> 5;
    int lane = tid & 31;
    int wm = wid >> 1;     // 0..3
    int wn = wid & 1;      // 0..1
    int m0 = blockIdx.x * 256;
    int n0 = blockIdx.y * 128;
    const bool isv = (n0 >= QK_COLS);   // uniform per CTA

    const size_t rs = (size_t)K * 2;
    const char* pAhi = (const char*)Ahi + (size_t)m0 * rs;
    const char* pAlo = (const char*)Alo + (size_t)m0 * rs;
    const char* pB   = (const char*)B   + (size_t)n0 * rs;

    auto load_chunk = [&](int stage, int c) {
        uint32_t base = sb + stage * G_STAGE;
        size_t kb = (size_t)c * 64;
#pragma unroll
        for (int i = 0; i < 8; i++) {
            if (i >= 4 && isv) break;   // skip A-lo loads for V tiles
            int f   = tid + i * 256;
            int arr = f >> 10;
            int rem = f & 1023;
            int row = rem >> 2;
            int seg = (rem & 3) * 16;
            uint32_t so = (uint32_t)(row * ROWB + seg) + (arr ? G_ALO : G_AHI);
            const char* p = (arr ? pAlo : pAhi) + (size_t)row * rs + kb + seg;
            cp16(base + so, p);
        }
#pragma unroll
        for (int i = 0; i < 2; i++) {
            int f   = tid + i * 256;
            int row = f >> 2;
            int seg = (f & 3) * 16;
            cp16(base + G_B + (uint32_t)(row * ROWB + seg),
                 pB + (size_t)row * rs + kb + seg);
        }
        asm volatile("cp.async.commit_group;" ::: "memory");
    };

    float acc[32][4];
#pragma unroll
    for (int t = 0; t < 32; t++)
#pragma unroll
        for (int j = 0; j < 4; j++) acc[t][j] = 0.0f;

    uint32_t a_off  = (uint32_t)((wm * 64 + (lane & 15)) * ROWB + (lane >> 4) * 16);
    uint32_t b_base = (uint32_t)((wn * 64 + (lane & 7) + ((lane >> 4) << 3)) * ROWB
                                 + ((lane >> 3) & 1) * 16);

    int nch = K / 32;
    load_chunk(0, 0);
    load_chunk(1, 1);
    load_chunk(2, 2);

    for (int c = 0; c < nch; c++) {
        asm volatile("cp.async.wait_group 2;" ::: "memory");
        __syncthreads();
        if (c + 3 < nch) load_chunk((c + 3) & 3, c + 3);
        else asm volatile("cp.async.commit_group;" ::: "memory");

        uint32_t tb = sb + (c & 3) * G_STAGE;
#pragma unroll
        for (int ks = 0; ks < 2; ks++) {
            uint32_t ko = (uint32_t)(ks * 32);
            uint32_t bh[4][4];
#pragma unroll
            for (int np = 0; np < 4; np++) {
                uint32_t bo = b_base + ko + (uint32_t)(np * 16 * ROWB);
                ldsm_x4(bh[np][0], bh[np][1], bh[np][2], bh[np][3], tb + G_B + bo);
            }
#pragma unroll
            for (int mt = 0; mt < 4; mt++) {
                uint32_t ah[4];
                uint32_t ao = a_off + ko + (uint32_t)(mt * 16 * ROWB);
                ldsm_x4(ah[0], ah[1], ah[2], ah[3], tb + G_AHI + ao);
#pragma unroll
                for (int np = 0; np < 4; np++) {
                    mma16816(acc[mt * 8 + 2 * np],     ah, bh[np]);
                    mma16816(acc[mt * 8 + 2 * np + 1], ah, bh[np] + 2);
                }
            }
            if (!isv) {
#pragma unroll
                for (int mt = 0; mt < 4; mt++) {
                    uint32_t al[4];
                    uint32_t ao = a_off + ko + (uint32_t)(mt * 16 * ROWB);
                    ldsm_x4(al[0], al[1], al[2], al[3], tb + G_ALO + ao);
#pragma unroll
                    for (int np = 0; np < 4; np++) {
                        mma16816(acc[mt * 8 + 2 * np],     al, bh[np]);
                        mma16816(acc[mt * 8 + 2 * np + 1], al, bh[np] + 2);
                    }
                }
            }
        }
    }

    int mbase = m0 + wm * 64 + (lane >> 2);
    int nbase = n0 + wn * 64 + (lane & 3) * 2;
    if (!isv) {
#pragma unroll
        for (int mt = 0; mt < 4; mt++) {
#pragma unroll
            for (int nt = 0; nt < 8; nt++) {
                float* d = acc[mt * 8 + nt];
                int r = mbase + mt * 16;
                int cc = nbase + nt * 8;
                *(float2*)(Cf + (size_t)r * ldc + cc)       = make_float2(d[0], d[1]);
                *(float2*)(Cf + (size_t)(r + 8) * ldc + cc) = make_float2(d[2], d[3]);
            }
        }
    } else {
#pragma unroll
        for (int mt = 0; mt < 4; mt++) {
#pragma unroll
            for (int nt = 0; nt < 8; nt++) {
                float* d = acc[mt * 8 + nt];
                int r = mbase + mt * 16;
                int cc = nbase + nt * 8;
                *(uint32_t*)(Ch + (size_t)r * ldc + cc)       = pack_f16x2(d[0], d[1]);
                *(uint32_t*)(Ch + (size_t)(r + 8) * ldc + cc) = pack_f16x2(d[2], d[3]);
            }
        }
    }
}

// ---------------------------------------------------------------------------
// 1-pass fp16 GEMM via mma.sync (NT), fp32 output.   [O-projection]
// ---------------------------------------------------------------------------
#define H_A 0
#define H_B (256 * ROWB)                // 20480
#define H_STAGE (H_B + 128 * ROWB)      // 30720
#define GEMM1_SMEM (4 * H_STAGE)        // 122880

__global__ __launch_bounds__(256, 1) void gemm_mma_kernel(
    const __half* __restrict__ A, const __half* __restrict__ B,
    float* __restrict__ C, int K, int ldc)
{
    extern __shared__ char smc[];
    uint32_t sb = smem_u32(smc);
    int tid  = threadIdx.x;
    int wid  = tid >> 5;
    int lane = tid & 31;
    int wm = wid >> 1;
    int wn = wid & 1;
    int m0 = blockIdx.x * 256;
    int n0 = blockIdx.y * 128;

    const size_t rs = (size_t)K * 2;
    const char* pA = (const char*)A + (size_t)m0 * rs;
    const char* pB = (const char*)B + (size_t)n0 * rs;

    auto load_chunk = [&](int stage, int c) {
        uint32_t base = sb + stage * H_STAGE;
        size_t kb = (size_t)c * 64;
#pragma unroll
        for (int i = 0; i < 4; i++) {
            int f   = tid + i * 256;
            int row = f >> 2;
            int seg = (f & 3) * 16;
            cp16(base + H_A + (uint32_t)(row * ROWB + seg),
                 pA + (size_t)row * rs + kb + seg);
        }
#pragma unroll
        for (int i = 0; i < 2; i++) {
            int f   = tid + i * 256;
            int row = f >> 2;
            int seg = (f & 3) * 16;
            cp16(base + H_B + (uint32_t)(row * ROWB + seg),
                 pB + (size_t)row * rs + kb + seg);
        }
        asm volatile("cp.async.commit_group;" ::: "memory");
    };

    float acc[32][4];
#pragma unroll
    for (int t = 0; t < 32; t++)
#pragma unroll
        for (int j = 0; j < 4; j++) acc[t][j] = 0.0f;

    uint32_t a_off  = (uint32_t)((wm * 64 + (lane & 15)) * ROWB + (lane >> 4) * 16);
    uint32_t b_base = (uint32_t)((wn * 64 + (lane & 7) + ((lane >> 4) << 3)) * ROWB
                                 + ((lane >> 3) & 1) * 16);

    int nch = K / 32;
    load_chunk(0, 0);
    load_chunk(1, 1);
    load_chunk(2, 2);

    for (int c = 0; c < nch; c++) {
        asm volatile("cp.async.wait_group 2;" ::: "memory");
        __syncthreads();
        if (c + 3 < nch) load_chunk((c + 3) & 3, c + 3);
        else asm volatile("cp.async.commit_group;" ::: "memory");

        uint32_t tb = sb + (c & 3) * H_STAGE;
#pragma unroll
        for (int ks = 0; ks < 2; ks++) {
            uint32_t ko = (uint32_t)(ks * 32);
            uint32_t bh[4][4];
#pragma unroll
            for (int np = 0; np < 4; np++) {
                uint32_t bo = b_base + ko + (uint32_t)(np * 16 * ROWB);
                ldsm_x4(bh[np][0], bh[np][1], bh[np][2], bh[np][3], tb + H_B + bo);
            }
#pragma unroll
            for (int mt = 0; mt < 4; mt++) {
                uint32_t ah[4];
                uint32_t ao = a_off + ko + (uint32_t)(mt * 16 * ROWB);
                ldsm_x4(ah[0], ah[1], ah[2], ah[3], tb + H_A + ao);
#pragma unroll
                for (int np = 0; np < 4; np++) {
                    mma16816(acc[mt * 8 + 2 * np],     ah, bh[np]);
                    mma16816(acc[mt * 8 + 2 * np + 1], ah, bh[np] + 2);
                }
            }
        }
    }

    int mbase = m0 + wm * 64 + (lane >> 2);
    int nbase = n0 + wn * 64 + (lane & 3) * 2;
#pragma unroll
    for (int mt = 0; mt < 4; mt++) {
#pragma unroll
        for (int nt = 0; nt < 8; nt++) {
            float* d = acc[mt * 8 + nt];
            int r = mbase + mt * 16;
            int cc = nbase + nt * 8;
            *(float2*)(C + (size_t)r * ldc + cc)       = make_float2(d[0], d[1]);
            *(float2*)(C + (size_t)(r + 8) * ldc + cc) = make_float2(d[2], d[3]);
        }
    }
}

// ---------------------------------------------------------------------------
// Tensor-core flash attention (causal, GQA).
// QK^T: 2-pass (Q hi+lo, K single).  PV: 1-pass.  Output: single fp16.
// Double-buffered K/V, Q fragments register-cached.  (verified R9/R13)
// ---------------------------------------------------------------------------
#define AROWB 272
#define A_QH 0
#define A_QL (128 * AROWB)                  // 34816
#define A_KV0 (2 * 128 * AROWB)             // 69632
#define KV_VOFF (64 * AROWB)                // 17408
#define KV_STAGE (128 * AROWB)              // 34816
#define ATTN_SMEM (A_KV0 + 2 * KV_STAGE)    // 139264

__global__ __launch_bounds__(256, 1) void attn_mma_kernel(
    const __half* __restrict__ qhi, const __half* __restrict__ qlo,
    __half* __restrict__ o)
{
    extern __shared__ char smc[];
    uint32_t sb = smem_u32(smc);
    int tid  = threadIdx.x;
    int w    = tid >> 5;
    int lane = tid & 31;
    int h    = blockIdx.y;
    int bx   = (int)gridDim.x - 1 - (int)blockIdx.x;   // heavy tiles first
    int q0   = bx * 128;
    int kvh  = h >> 2;

    auto load_kv = [&](int stage, int kt) {
        int k0 = kt * 64;
        uint32_t kbase = sb + A_KV0 + stage * KV_STAGE;
#pragma unroll
        for (int i = 0; i < 8; i++) {
            int f   = tid + i * 256;
            int arr = f >> 10;          // 0 K, 1 V
            int rem = f & 1023;
            int row = rem >> 4;
            int seg = rem & 15;
            int off = arr ? (HID + NKV * HD) : HID;
            const __half* src =
                qhi + (size_t)(k0 + row) * QKV_DIM + off + kvh * HD + seg * 8;
            cp16(kbase + (arr ? KV_VOFF : 0) + row * AROWB + seg * 16, src);
        }
        asm volatile("cp.async.commit_group;" ::: "memory");
    };

    // Q tile hi+lo, committed together with KV tile 0
#pragma unroll
    for (int i = 0; i < 16; i++) {
        int f   = tid + i * 256;
        int arr = f >> 11;
        int rem = f & 2047;
        int row = rem >> 4;
        int seg = rem & 15;
        const __half* src =
            (arr ? qlo : qhi) + (size_t)(q0 + row) * QKV_DIM + h * HD + seg * 8;
        cp16(sb + (arr ? A_QL : A_QH) + row * AROWB + seg * 16, src);
    }
    load_kv(0, 0);
    load_kv(1, 1);

    asm volatile("cp.async.wait_group 1;" ::: "memory");
    __syncthreads();

    // cache Q fragments in registers (loaded once)
    uint32_t qfh[8][4], qfl[8][4];
#pragma unroll
    for (int ks = 0; ks < 8; ks++) {
        uint32_t ao = (uint32_t)((16 * w + (lane & 15)) * AROWB
                                 + ks * 32 + (lane >> 4) * 16);
        ldsm_x4(qfh[ks][0], qfh[ks][1], qfh[ks][2], qfh[ks][3], sb + A_QH + ao);
        ldsm_x4(qfl[ks][0], qfl[ks][1], qfl[ks][2], qfl[ks][3], sb + A_QL + ao);
    }

    float oacc[16][4];
#pragma unroll
    for (int t = 0; t < 16; t++)
#pragma unroll
        for (int j = 0; j < 4; j++) oacc[t][j] = 0.0f;
    float mrow[2] = {-1e30f, -1e30f};
    float lrow[2] = {0.0f, 0.0f};

    int wmin = q0 + 16 * w;
    int nkt  = 2 * (bx + 1);

    for (int kt = 0; kt < nkt; kt++) {
        int buf = kt & 1;
        int k0  = kt * 64;

        if (k0 <= wmin + 15) {
            uint32_t kvb = sb + A_KV0 + buf * KV_STAGE;
            float sacc[8][4];
#pragma unroll
            for (int t = 0; t < 8; t++)
#pragma unroll
                for (int j = 0; j < 4; j++) sacc[t][j] = 0.0f;

            // ---- S = Q . K^T (2 passes, Q from registers)
#pragma unroll
            for (int ks = 0; ks < 8; ks++) {
#pragma unroll
                for (int np = 0; np < 4; np++) {
                    uint32_t kh_[4];
                    uint32_t bo = (uint32_t)((np * 16 + (lane & 7)
                                              + ((lane >> 4) << 3)) * AROWB
                                             + ks * 32 + ((lane >> 3) & 1) * 16);
                    ldsm_x4(kh_[0], kh_[1], kh_[2], kh_[3], kvb + bo);
                    mma16816(sacc[2 * np],     qfh[ks], kh_);
                    mma16816(sacc[2 * np],     qfl[ks], kh_);
                    mma16816(sacc[2 * np + 1], qfh[ks], kh_ + 2);
                    mma16816(sacc[2 * np + 1], qfl[ks], kh_ + 2);
                }
            }

            // ---- scale
#pragma unroll
            for (int nt = 0; nt < 8; nt++)
#pragma unroll
                for (int j = 0; j < 4; j++) sacc[nt][j] *= SCALE;

            // ---- causal mask
            int r1 = wmin + (lane >> 2);
            if (k0 + 63 > wmin) {
#pragma unroll
                for (int nt = 0; nt < 8; nt++) {
                    int c0 = k0 + nt * 8 + (lane & 3) * 2;
                    if (c0     > r1)     sacc[nt][0] = -1e30f;
                    if (c0 + 1 > r1)     sacc[nt][1] = -1e30f;
                    if (c0     > r1 + 8) sacc[nt][2] = -1e30f;
                    if (c0 + 1 > r1 + 8) sacc[nt][3] = -1e30f;
                }
            }

            // ---- online softmax
#pragma unroll
            for (int hf = 0; hf < 2; hf++) {
                float mx = -1e30f;
#pragma unroll
                for (int nt = 0; nt < 8; nt++)
                    mx = fmaxf(mx, fmaxf(sacc[nt][2 * hf], sacc[nt][2 * hf + 1]));
                mx = fmaxf(mx, __shfl_xor_sync(0xffffffffu, mx, 1));
                mx = fmaxf(mx, __shfl_xor_sync(0xffffffffu, mx, 2));
                float mn   = fmaxf(mrow[hf], mx);
                float corr = __expf(mrow[hf] - mn);
                mrow[hf] = mn;
                float sum = 0.0f;
#pragma unroll
                for (int nt = 0; nt < 8; nt++) {
                    float p0 = __expf(sacc[nt][2 * hf]     - mn);
                    float p1 = __expf(sacc[nt][2 * hf + 1] - mn);
                    sacc[nt][2 * hf]     = p0;
                    sacc[nt][2 * hf + 1] = p1;
                    sum += p0 + p1;
                }
                sum += __shfl_xor_sync(0xffffffffu, sum, 1);
                sum += __shfl_xor_sync(0xffffffffu, sum, 2);
                lrow[hf] = lrow[hf] * corr + sum;
#pragma unroll
                for (int nt = 0; nt < 16; nt++) {
                    oacc[nt][2 * hf]     *= corr;
                    oacc[nt][2 * hf + 1] *= corr;
                }
            }

            // ---- O += P . V (1 pass)
#pragma unroll
            for (int j = 0; j < 4; j++) {
                uint32_t ph_[4];
                ph_[0] = pack_f16x2(sacc[2 * j][0],     sacc[2 * j][1]);
                ph_[1] = pack_f16x2(sacc[2 * j][2],     sacc[2 * j][3]);
                ph_[2] = pack_f16x2(sacc[2 * j + 1][0], sacc[2 * j + 1][1]);
                ph_[3] = pack_f16x2(sacc[2 * j + 1][2], sacc[2 * j + 1][3]);
#pragma unroll
                for (int np = 0; np < 8; np++) {
                    uint32_t vh_[4];
                    uint32_t vo = (uint32_t)((j * 16 + (lane & 7)
                                              + ((lane >> 3) & 1) * 8) * AROWB
                                             + (np * 16 + ((lane >> 4) << 3)) * 2);
                    ldsm_x4t(vh_[0], vh_[1], vh_[2], vh_[3], kvb + KV_VOFF + vo);
                    mma16816(oacc[2 * np],     ph_, vh_);
                    mma16816(oacc[2 * np + 1], ph_, vh_ + 2);
                }
            }
        }
        __syncthreads();

        if (kt + 2 < nkt) load_kv(buf, kt + 2);
        if (kt + 1 < nkt) {
            asm volatile("cp.async.wait_group %0;" :: "n"(1) : "memory");
        }
        if (kt + 1 < nkt && kt + 2 >= nkt) {
            asm volatile("cp.async.wait_group 0;" ::: "memory");
        }
        if (kt + 1 < nkt) __syncthreads();
    }

    // ---- epilogue: normalize + single fp16 write
    float inv0 = 1.0f / lrow[0];
    float inv1 = 1.0f / lrow[1];
    int r1 = q0 + 16 * w + (lane >> 2);
    size_t base1 = (size_t)r1 * HID + h * HD + (lane & 3) * 2;
    size_t base2 = base1 + (size_t)8 * HID;
#pragma unroll
    for (int nt = 0; nt < 16; nt++) {
        *(uint32_t*)(o + base1 + nt * 8) =
            pack_f16x2(oacc[nt][0] * inv0, oacc[nt][1] * inv0);
        *(uint32_t*)(o + base2 + nt * 8) =
            pack_f16x2(oacc[nt][2] * inv1, oacc[nt][3] * inv1);
    }
}

// ---------------------------------------------------------------------------
// Launch
// ---------------------------------------------------------------------------
extern "C" void kernel_launch(void* const* d_in, const int* in_sizes, int n_in,
                              void* d_out, int out_size)
{
    (void)in_sizes; (void)n_in; (void)out_size;
    const float* x     = (const float*)d_in[0];
    const int*   pos   = (const int*)d_in[1];
    const float* w_qkv = (const float*)d_in[2];
    const float* w_o   = (const float*)d_in[3];
    float*       out   = (float*)d_out;

    void *p_qkv, *p_xh, *p_xl, *p_wq, *p_wo, *p_sph, *p_spl, *p_attn;
    cudaGetSymbolAddress(&p_qkv, g_qkv);
    cudaGetSymbolAddress(&p_xh, g_x_hi);
    cudaGetSymbolAddress(&p_xl, g_x_lo);
    cudaGetSymbolAddress(&p_wq, g_wqkv);
    cudaGetSymbolAddress(&p_wo, g_wo);
    cudaGetSymbolAddress(&p_sph, g_qkvsp_hi);
    cudaGetSymbolAddress(&p_spl, g_qkvsp_lo);
    cudaGetSymbolAddress(&p_attn, g_attn);
    float* qkv = (float*)p_qkv;

    cudaFuncSetAttribute(gemm_qkv_fused_kernel,
                         cudaFuncAttributeMaxDynamicSharedMemorySize, GEMM_SMEM);
    cudaFuncSetAttribute(gemm_mma_kernel,
                         cudaFuncAttributeMaxDynamicSharedMemorySize, GEMM1_SMEM);
    cudaFuncSetAttribute(attn_mma_kernel,
                         cudaFuncAttributeMaxDynamicSharedMemorySize, ATTN_SMEM);

    // RoPE table
    rope_table_kernel<<<(S_LEN * 64 + 255) / 256, 256>>>(pos);

    // Converts
    {
        int n1 = S_LEN * HID / 8;
        convert_split_kernel<<<(n1 + 255) / 256, 256>>>(
            x, (__half*)p_xh, (__half*)p_xl, n1);
        int n2 = QKV_DIM * HID / 8;
        convert_half_kernel<<<(n2 + 255) / 256, 256>>>(w_qkv, (__half*)p_wq, n2);
        int n3 = HID * HID / 8;
        convert_half_kernel<<<(n3 + 255) / 256, 256>>>(w_o, (__half*)p_wo, n3);
    }

    // Fused QKV projection: q,k 2-pass fp32 out; v 1-pass fp16 out.
    gemm_qkv_fused_kernel<<<dim3(S_LEN / 256, QKV_DIM / 128), 256, GEMM_SMEM>>>(
        (const __half*)p_xh, (const __half*)p_xl, (const __half*)p_wq,
        qkv, (__half*)p_sph, HID, QKV_DIM);

    // RoPE + split q,k
    postqkv_kernel<<<(S_LEN * 40 * 32 + 255) / 256, 256>>>(
        qkv, (__half*)p_sph, (__half*)p_spl);

    // Tensor-core flash attention (single-fp16 output)
    attn_mma_kernel<<<dim3(S_LEN / 128, NH), 256, ATTN_SMEM>>>(
        (const __half*)p_sph, (const __half*)p_spl, (__half*)p_attn);

    // Output projection (1-pass, fp32 out)
    gemm_mma_kernel<<<dim3(S_LEN / 256, HID / 128), 256, GEMM1_SMEM>>>(
        (const __half*)p_attn, (const __half*)p_wo, out, HID, HID);
}